// round 1
// baseline (speedup 1.0000x reference)
#include <cuda_runtime.h>
#include <cuda_bf16.h>
#include <math.h>

// ---------------------------------------------------------------------------
// LogicRecursiveNN: leaf gather -> 6x two2one MLP tree levels -> one2one MLP
//                   -> theorem head (3 GEMMs + final dot + sigmoid)
// All heavy work is plain GEMMs on flattened contiguous buffers.
// Round 1: fp32 SIMT tiled SGEMM (128x128x16, 8x8 per-thread register tile).
// ---------------------------------------------------------------------------

#define B_    512
#define NT_   2
#define NL_   64
#define E_    512
#define T_    512

// scratch (static __device__ arrays; no runtime allocation allowed)
__device__ float g_bufA[(size_t)B_ * NT_ * NL_ * E_];      // 33,554,432 floats
__device__ float g_bufB[(size_t)B_ * NT_ * NL_ * E_ / 2];  // 16,777,216 floats
__device__ float g_bufH[(size_t)B_ * NT_ * (NL_/2) * 4 * E_]; // 67,108,864 floats
__device__ float g_feat[(size_t)B_ * (T_ + NT_ * E_)];     // 512*1536
__device__ float g_z1[(size_t)B_ * E_];                    // 512*512
__device__ float g_z2[(size_t)B_ * (E_/2)];                // 512*256
__device__ float g_z3[(size_t)B_ * (E_/4)];                // 512*128

// ---------------------------------------------------------------------------
// Gather: out[row, :] = ent_emb[leaf_idx[row], :]   (row = b*NT*NL + t*NL + l)
// One block per row, 128 threads, each moves one float4 (512 floats/row).
// ---------------------------------------------------------------------------
__global__ void gather_kernel(const int* __restrict__ idx,
                              const float* __restrict__ emb,
                              float* __restrict__ out)
{
    const int row = blockIdx.x;
    const int e = idx[row];
    const float4 v = ((const float4*)(emb + (size_t)e * E_))[threadIdx.x];
    ((float4*)(out + (size_t)row * E_))[threadIdx.x] = v;
}

// ---------------------------------------------------------------------------
// SGEMM: C[M,N] = act(A[M,K] @ B[K,N] + bias[N])
// Requirements (all satisfied here): M%128==0, N%128==0, K%16==0.
// BM=BN=128, BK=16, 256 threads, 8x8 accumulators per thread (split 4+4).
// ---------------------------------------------------------------------------
#define ACT_RELU 0
#define ACT_TANH 1

template <int ACT>
__device__ __forceinline__ float apply_act(float x) {
    if (ACT == ACT_RELU) return fmaxf(x, 0.0f);
    return tanhf(x);
}

template <int ACT>
__global__ void __launch_bounds__(256, 1)
sgemm128(const float* __restrict__ A, const float* __restrict__ Bm,
         const float* __restrict__ bias, float* __restrict__ C,
         int M, int N, int K)
{
    constexpr int BK = 16;
    __shared__ float As[BK][128];   // transposed A tile: As[k][m]
    __shared__ float Bs[BK][128];   // Bs[k][n]

    const int tid = threadIdx.x;
    const int tx = tid & 15;        // 16 threads along N
    const int ty = tid >> 4;        // 16 threads along M

    const long row0 = (long)blockIdx.y * 128;
    const int  col0 = blockIdx.x * 128;

    const float* Ab = A + row0 * K;
    const float* Bb = Bm + col0;

    float acc[8][8];
#pragma unroll
    for (int i = 0; i < 8; i++)
#pragma unroll
        for (int j = 0; j < 8; j++) acc[i][j] = 0.0f;

    for (int k0 = 0; k0 < K; k0 += BK) {
        // load A tile [128 x 16] (float4 per thread x2), store transposed
#pragma unroll
        for (int i = 0; i < 2; i++) {
            const int l = tid + i * 256;         // 0..511
            const int r = l >> 2;                // row 0..127
            const int c = (l & 3) << 2;          // k-offset 0,4,8,12
            const float4 v = *(const float4*)(Ab + (long)r * K + (k0 + c));
            As[c + 0][r] = v.x;
            As[c + 1][r] = v.y;
            As[c + 2][r] = v.z;
            As[c + 3][r] = v.w;
        }
        // load B tile [16 x 128]
#pragma unroll
        for (int i = 0; i < 2; i++) {
            const int l = tid + i * 256;         // 0..511
            const int r = l >> 5;                // k row 0..15
            const int c = (l & 31) << 2;         // col 0..124
            *(float4*)&Bs[r][c] = *(const float4*)(Bb + (long)(k0 + r) * N + c);
        }
        __syncthreads();

#pragma unroll
        for (int k = 0; k < BK; k++) {
            float a[8], b[8];
            *(float4*)&a[0] = *(const float4*)&As[k][ty * 4];
            *(float4*)&a[4] = *(const float4*)&As[k][64 + ty * 4];
            *(float4*)&b[0] = *(const float4*)&Bs[k][tx * 4];
            *(float4*)&b[4] = *(const float4*)&Bs[k][64 + tx * 4];
#pragma unroll
            for (int i = 0; i < 8; i++)
#pragma unroll
                for (int j = 0; j < 8; j++)
                    acc[i][j] = fmaf(a[i], b[j], acc[i][j]);
        }
        __syncthreads();
    }

    // epilogue: bias + activation, vectorized stores
    float blo[4], bhi[4];
    *(float4*)blo = *(const float4*)(bias + col0 + tx * 4);
    *(float4*)bhi = *(const float4*)(bias + col0 + 64 + tx * 4);

#pragma unroll
    for (int i = 0; i < 8; i++) {
        const int r = (i < 4) ? (ty * 4 + i) : (64 + ty * 4 + (i - 4));
        float* Cp = C + (row0 + r) * (long)N + col0;
        float4 v;
        v.x = apply_act<ACT>(acc[i][0] + blo[0]);
        v.y = apply_act<ACT>(acc[i][1] + blo[1]);
        v.z = apply_act<ACT>(acc[i][2] + blo[2]);
        v.w = apply_act<ACT>(acc[i][3] + blo[3]);
        *(float4*)(Cp + tx * 4) = v;
        v.x = apply_act<ACT>(acc[i][4] + bhi[0]);
        v.y = apply_act<ACT>(acc[i][5] + bhi[1]);
        v.z = apply_act<ACT>(acc[i][6] + bhi[2]);
        v.w = apply_act<ACT>(acc[i][7] + bhi[3]);
        *(float4*)(Cp + 64 + tx * 4) = v;
    }
}

// ---------------------------------------------------------------------------
// feat[b, 0:512]    = th_emb
// feat[b, 512:1536] = root2[b, :]  (root2 is [B, NT*E] contiguous)
// 512 blocks x 384 threads, one float4 per thread (1536 floats / row).
// ---------------------------------------------------------------------------
__global__ void feat_kernel(const float* __restrict__ th,
                            const float* __restrict__ root2,
                            float* __restrict__ feat)
{
    const int b = blockIdx.x;
    const int t = threadIdx.x;  // 0..383
    float4 v;
    if (t < T_ / 4) v = ((const float4*)th)[t];
    else            v = ((const float4*)(root2 + (size_t)b * (NT_ * E_)))[t - T_ / 4];
    ((float4*)(feat + (size_t)b * (T_ + NT_ * E_)))[t] = v;
}

// ---------------------------------------------------------------------------
// Final: out[r] = sigmoid(dot(z3[r, 0:128], w) + b0).  One warp per row.
// ---------------------------------------------------------------------------
__global__ void final_kernel(const float* __restrict__ z3,
                             const float* __restrict__ w,
                             const float* __restrict__ b0,
                             float* __restrict__ out)
{
    const int warp = (blockIdx.x * blockDim.x + threadIdx.x) >> 5;
    const int lane = threadIdx.x & 31;
    if (warp >= B_) return;
    const float* zr = z3 + (size_t)warp * 128;
    float s = 0.0f;
#pragma unroll
    for (int i = lane; i < 128; i += 32) s = fmaf(zr[i], w[i], s);
#pragma unroll
    for (int o = 16; o > 0; o >>= 1) s += __shfl_down_sync(0xFFFFFFFFu, s, o);
    if (lane == 0) {
        const float x = s + b0[0];
        out[warp] = 1.0f / (1.0f + expf(-x));
    }
}

// ---------------------------------------------------------------------------
// launch
// ---------------------------------------------------------------------------
static inline dim3 gemm_grid(int M, int N) { return dim3(N / 128, M / 128); }

extern "C" void kernel_launch(void* const* d_in, const int* in_sizes, int n_in,
                              void* d_out, int out_size)
{
    const int*   leaf = (const int*)  d_in[0];
    const float* ent  = (const float*)d_in[1];
    const float* th   = (const float*)d_in[2];
    const float* w1   = (const float*)d_in[3];
    const float* b1   = (const float*)d_in[4];
    const float* w2   = (const float*)d_in[5];
    const float* b2   = (const float*)d_in[6];
    const float* o1   = (const float*)d_in[7];
    const float* ob1  = (const float*)d_in[8];
    const float* o2   = (const float*)d_in[9];
    const float* ob2  = (const float*)d_in[10];
    const float* h1   = (const float*)d_in[11];
    const float* hb1  = (const float*)d_in[12];
    const float* h2   = (const float*)d_in[13];
    const float* hb2  = (const float*)d_in[14];
    const float* h3   = (const float*)d_in[15];
    const float* hb3  = (const float*)d_in[16];
    const float* h4   = (const float*)d_in[17];
    const float* hb4  = (const float*)d_in[18];

    float *bufA, *bufB, *H, *feat, *z1, *z2, *z3;
    cudaGetSymbolAddress((void**)&bufA, g_bufA);
    cudaGetSymbolAddress((void**)&bufB, g_bufB);
    cudaGetSymbolAddress((void**)&H,    g_bufH);
    cudaGetSymbolAddress((void**)&feat, g_feat);
    cudaGetSymbolAddress((void**)&z1,   g_z1);
    cudaGetSymbolAddress((void**)&z2,   g_z2);
    cudaGetSymbolAddress((void**)&z3,   g_z3);

    // 1) leaf embedding gather -> bufA : [B*NT*NL, E]
    gather_kernel<<<B_ * NT_ * NL_, E_ / 4>>>(leaf, ent, bufA);

    // 2) tree reduction: 6 levels of two2one (ReLU, ReLU)
    float* in  = bufA;
    float* out = bufB;
    int n = NL_;
    while (n > 1) {
        const int rows = B_ * NT_ * (n / 2);   // view input as [rows, 2E]
        // h = relu(in @ w1 + b1)  : [rows, 4E]
        sgemm128<ACT_RELU><<<gemm_grid(rows, 4 * E_), 256>>>(in, w1, b1, H, rows, 4 * E_, 2 * E_);
        // out = relu(h @ w2 + b2) : [rows, E]
        sgemm128<ACT_RELU><<<gemm_grid(rows, E_), 256>>>(H, w2, b2, out, rows, E_, 4 * E_);
        float* t = in; in = out; out = t;
        n >>= 1;
    }
    // root is now in `in` : [B*NT, E] = [1024, 512]

    // 3) one2one: relu(root @ o1 + ob1) -> H ; tanh(H @ o2 + ob2) -> out
    {
        const int rows = B_ * NT_;
        sgemm128<ACT_RELU><<<gemm_grid(rows, 4 * E_), 256>>>(in, o1, ob1, H, rows, 4 * E_, E_);
        sgemm128<ACT_TANH><<<gemm_grid(rows, E_), 256>>>(H, o2, ob2, out, rows, E_, 4 * E_);
    }
    // `out` holds root2 : [B, NT*E] contiguous

    // 4) feat = [th_emb | root2] : [B, 1536]
    feat_kernel<<<B_, (T_ + NT_ * E_) / 4>>>(th, out, feat);

    // 5) head
    sgemm128<ACT_RELU><<<gemm_grid(B_, E_),      256>>>(feat, h1, hb1, z1, B_, E_,      T_ + NT_ * E_);
    sgemm128<ACT_RELU><<<gemm_grid(B_, E_ / 2),  256>>>(z1,   h2, hb2, z2, B_, E_ / 2,  E_);
    sgemm128<ACT_RELU><<<gemm_grid(B_, E_ / 4),  256>>>(z2,   h3, hb3, z3, B_, E_ / 4,  E_ / 2);

    // 6) final dot + sigmoid -> d_out [512]
    final_kernel<<<(B_ * 32 + 255) / 256, 256>>>(z3, h4, hb4, (float*)d_out);
}

// round 3
// speedup vs baseline: 2.0782x; 2.0782x over previous
#include <cuda_runtime.h>
#include <cuda_bf16.h>
#include <math.h>
#include <stdint.h>

// ===========================================================================
// LogicRecursiveNN on GB300 (plain sm_103 PTX target -> no tcgen05).
// bf16 mma.sync (m16n8k16) GEMMs with 3-pass error compensation:
//   every tensor is stored as two bf16 planes (hi, lo), x ~= hi + lo.
//   D += Ah*Bh + Ah*Bl + Al*Bh    (error ~2^-17 per element)
// Mainloop: cp.async -> ldmatrix -> mma.sync. No conversions in the loop.
// ===========================================================================

#define B_    512
#define NT_   2
#define NL_   64
#define E_    512
#define T_    512

// plane strides (elements)
#define SA_   ((size_t)B_ * NT_ * NL_ * E_)        // 33,554,432
#define SB_   ((size_t)B_ * NT_ * NL_ * E_ / 2)    // 16,777,216
#define SH_   ((size_t)B_ * NT_ * (NL_/2) * 4 * E_)// 67,108,864
#define SF_   ((size_t)B_ * (T_ + NT_ * E_))       // 786,432
#define SZ1_  ((size_t)B_ * E_)
#define SZ2_  ((size_t)B_ * (E_/2))
#define SZ3_  ((size_t)B_ * (E_/4))
#define WPS_  6193152                              // weight pool plane stride

// device scratch: dual-plane bf16 buffers
__device__ __nv_bfloat16 g_bufA[2 * SA_];
__device__ __nv_bfloat16 g_bufB[2 * SB_];
__device__ __nv_bfloat16 g_bufH[2 * SH_];
__device__ __nv_bfloat16 g_feat[2 * SF_];
__device__ __nv_bfloat16 g_z1[2 * SZ1_];
__device__ __nv_bfloat16 g_z2[2 * SZ2_];
__device__ __nv_bfloat16 g_z3[2 * SZ3_];
__device__ __nv_bfloat16 g_wT[2 * WPS_];

// weight offsets within a plane (elements)
#define W1T_OFF  0          // [2048,1024]
#define W2T_OFF  2097152    // [512,2048]
#define O1T_OFF  3145728    // [2048,512]
#define O2T_OFF  4194304    // [512,2048]
#define H1T_OFF  5242880    // [512,1536]
#define H2T_OFF  6029312    // [256,512]
#define H3T_OFF  6160384    // [128,256]

// ---------------------------------------------------------------------------
// helpers
// ---------------------------------------------------------------------------
__device__ __forceinline__ uint32_t smem_u32(const void* p) {
    uint32_t a;
    asm("{ .reg .u64 t; cvta.to.shared.u64 t, %1; cvt.u32.u64 %0, t; }"
        : "=r"(a) : "l"(p));
    return a;
}

__device__ __forceinline__ void split_bf16(float x, __nv_bfloat16& h, __nv_bfloat16& l) {
    h = __float2bfloat16_rn(x);
    l = __float2bfloat16_rn(x - __bfloat162float(h));
}

__device__ __forceinline__ void cp16(uint32_t dst, const void* src) {
    asm volatile("cp.async.cg.shared.global [%0], [%1], 16;"
                 :: "r"(dst), "l"(src) : "memory");
}
__device__ __forceinline__ void cp_commit() {
    asm volatile("cp.async.commit_group;" ::: "memory");
}
template <int N>
__device__ __forceinline__ void cp_wait() {
    asm volatile("cp.async.wait_group %0;" :: "n"(N) : "memory");
}

__device__ __forceinline__ void ldm_x4(uint32_t* r, uint32_t addr) {
    asm volatile("ldmatrix.sync.aligned.m8n8.x4.shared.b16 {%0,%1,%2,%3}, [%4];"
                 : "=r"(r[0]), "=r"(r[1]), "=r"(r[2]), "=r"(r[3]) : "r"(addr));
}
__device__ __forceinline__ void ldm_x2(uint32_t* r, uint32_t addr) {
    asm volatile("ldmatrix.sync.aligned.m8n8.x2.shared.b16 {%0,%1}, [%2];"
                 : "=r"(r[0]), "=r"(r[1]) : "r"(addr));
}

__device__ __forceinline__ void mma_bf16(float* c, const uint32_t* a, const uint32_t* b) {
    asm volatile(
        "mma.sync.aligned.m16n8k16.row.col.f32.bf16.bf16.f32 "
        "{%0,%1,%2,%3}, {%4,%5,%6,%7}, {%8,%9}, {%0,%1,%2,%3};"
        : "+f"(c[0]), "+f"(c[1]), "+f"(c[2]), "+f"(c[3])
        : "r"(a[0]), "r"(a[1]), "r"(a[2]), "r"(a[3]), "r"(b[0]), "r"(b[1]));
}

// ---------------------------------------------------------------------------
// small kernels
// ---------------------------------------------------------------------------
// gather: out planes [B*NT*NL, E], one block per row, 128 threads x float4
__global__ void gather_kernel(const int* __restrict__ idx,
                              const float* __restrict__ emb,
                              __nv_bfloat16* __restrict__ out)  // hi plane; lo = +SA_
{
    const int row = blockIdx.x;
    const int e = idx[row];
    const float4 v = ((const float4*)(emb + (size_t)e * E_))[threadIdx.x];
    __nv_bfloat16 h[4], l[4];
    split_bf16(v.x, h[0], l[0]); split_bf16(v.y, h[1], l[1]);
    split_bf16(v.z, h[2], l[2]); split_bf16(v.w, h[3], l[3]);
    const size_t o = (size_t)row * E_ + threadIdx.x * 4;
    *(uint2*)(out + o)       = *(uint2*)h;
    *(uint2*)(out + SA_ + o) = *(uint2*)l;
}

// W[K,N] f32 -> Wt_hi/lo [N,K] bf16; grid(N/32, K/32), block(32,8)
__global__ void transpose_kernel(const float* __restrict__ W,
                                 __nv_bfloat16* __restrict__ Wt,  // hi; lo = +WPS_
                                 int K, int N)
{
    __shared__ float t[32][33];
    const int bx = blockIdx.x * 32;   // n
    const int by = blockIdx.y * 32;   // k
    for (int i = threadIdx.y; i < 32; i += 8)
        t[i][threadIdx.x] = W[(size_t)(by + i) * N + bx + threadIdx.x];
    __syncthreads();
    for (int i = threadIdx.y; i < 32; i += 8) {
        const float x = t[threadIdx.x][i];
        __nv_bfloat16 h, l;
        split_bf16(x, h, l);
        const size_t o = (size_t)(bx + i) * K + by + threadIdx.x;
        Wt[o] = h;
        Wt[WPS_ + o] = l;
    }
}

// feat planes: [B,1536] = [th_emb | root2], root2 already dual-plane
__global__ void feat_kernel(const float* __restrict__ th,
                            const __nv_bfloat16* __restrict__ root2, // hi; lo=+SB_
                            __nv_bfloat16* __restrict__ feat)        // hi; lo=+SF_
{
    const int b = blockIdx.x;
    const int t = threadIdx.x;  // 0..383, 4 elems each
    const size_t o = (size_t)b * (T_ + NT_ * E_) + t * 4;
    if (t < T_ / 4) {
        const float4 v = ((const float4*)th)[t];
        __nv_bfloat16 h[4], l[4];
        split_bf16(v.x, h[0], l[0]); split_bf16(v.y, h[1], l[1]);
        split_bf16(v.z, h[2], l[2]); split_bf16(v.w, h[3], l[3]);
        *(uint2*)(feat + o)       = *(uint2*)h;
        *(uint2*)(feat + SF_ + o) = *(uint2*)l;
    } else {
        const size_t ro = (size_t)b * (NT_ * E_) + (t - T_ / 4) * 4;
        *(uint2*)(feat + o)       = *(const uint2*)(root2 + ro);
        *(uint2*)(feat + SF_ + o) = *(const uint2*)(root2 + SB_ + ro);
    }
}

// final: out[r] = sigmoid(dot(z3_hi[r]+z3_lo[r], w) + b0), one warp per row
__global__ void final_kernel(const __nv_bfloat16* __restrict__ z3, // hi; lo=+SZ3_
                             const float* __restrict__ w,
                             const float* __restrict__ b0,
                             float* __restrict__ out)
{
    const int warp = (blockIdx.x * blockDim.x + threadIdx.x) >> 5;
    const int lane = threadIdx.x & 31;
    if (warp >= B_) return;
    const size_t base = (size_t)warp * 128;
    float s = 0.0f;
#pragma unroll
    for (int i = lane; i < 128; i += 32) {
        const float x = __bfloat162float(z3[base + i]) + __bfloat162float(z3[SZ3_ + base + i]);
        s = fmaf(x, w[i], s);
    }
#pragma unroll
    for (int o = 16; o > 0; o >>= 1) s += __shfl_down_sync(0xFFFFFFFFu, s, o);
    if (lane == 0) {
        const float x = s + b0[0];
        out[warp] = 1.0f / (1.0f + expf(-x));
    }
}

// ---------------------------------------------------------------------------
// GEMM: C = act(A @ Bt^T + bias), all operands dual-plane bf16.
// CTA 128x128, 8 warps (2x4), warp tile 64x32, KC=32, 3-stage cp.async.
// ---------------------------------------------------------------------------
#define KC       32
#define STAGES   3
#define PITCH    80                          // bytes per smem row (32 bf16 + pad)
#define TILE_SB  (128 * PITCH)               // 10240 B
#define STAGE_SB (4 * TILE_SB)               // 40960 B (Ah, Al, Bh, Bl)
#define GSMEM    (STAGES * STAGE_SB)         // 122880 B

#define ACT_RELU 0
#define ACT_TANH 1

template <int ACT>
__device__ __forceinline__ float apply_act(float x) {
    if (ACT == ACT_RELU) return fmaxf(x, 0.0f);
    return tanhf(x);
}

template <int ACT>
__global__ void __launch_bounds__(256, 1)
gemm_mma(const __nv_bfloat16* __restrict__ A, size_t aps,
         const __nv_bfloat16* __restrict__ Bt, size_t bps,
         const float* __restrict__ bias,
         __nv_bfloat16* __restrict__ C, size_t cps,
         int M, int N, int K)
{
    extern __shared__ char smem[];
    const uint32_t sb = smem_u32(smem);
    const int tid = threadIdx.x;
    const int wid = tid >> 5;
    const int lane = tid & 31;
    const int wm = wid >> 2;        // 0..1  (M)
    const int wn = wid & 3;         // 0..3  (N)

    const size_t row0 = (size_t)blockIdx.y * 128;
    const size_t col0 = (size_t)blockIdx.x * 128;
    const __nv_bfloat16* Ah = A + row0 * K;
    const __nv_bfloat16* Bh = Bt + col0 * K;

    // cp.async mapping: 256 threads, seg = 16B chunk in row, rowc = row half
    const int seg = tid & 3;
    const int rowc = tid >> 2;      // 0..63

    const int nk = K / KC;

    // prologue
    for (int c = 0; c < STAGES - 1 && c < nk; c++) {
        const uint32_t st = sb + (c % STAGES) * STAGE_SB;
        const int k0 = c * KC;
#pragma unroll
        for (int h = 0; h < 2; h++) {
            const int r = rowc + h * 64;
            const size_t go = (size_t)r * K + k0 + seg * 8;
            const uint32_t so = r * PITCH + seg * 16;
            cp16(st + 0 * TILE_SB + so, Ah + go);
            cp16(st + 1 * TILE_SB + so, Ah + aps + go);
            cp16(st + 2 * TILE_SB + so, Bh + go);
            cp16(st + 3 * TILE_SB + so, Bh + bps + go);
        }
        cp_commit();
    }

    float acc[4][4][4];
#pragma unroll
    for (int i = 0; i < 4; i++)
#pragma unroll
        for (int j = 0; j < 4; j++)
#pragma unroll
            for (int k = 0; k < 4; k++) acc[i][j][k] = 0.0f;

    // ldmatrix base addresses (within a stage)
    const uint32_t aoff = (uint32_t)((wm * 64 + (lane & 15)) * PITCH + (lane >> 4) * 16);
    const uint32_t boff = (uint32_t)((wn * 32 + (lane & 7)) * PITCH + ((lane >> 3) & 1) * 16);

    for (int i = 0; i < nk; i++) {
        // issue stage i+STAGES-1
        if (i + STAGES - 1 < nk) {
            const int c = i + STAGES - 1;
            const uint32_t st = sb + (c % STAGES) * STAGE_SB;
            const int k0 = c * KC;
#pragma unroll
            for (int h = 0; h < 2; h++) {
                const int r = rowc + h * 64;
                const size_t go = (size_t)r * K + k0 + seg * 8;
                const uint32_t so = r * PITCH + seg * 16;
                cp16(st + 0 * TILE_SB + so, Ah + go);
                cp16(st + 1 * TILE_SB + so, Ah + aps + go);
                cp16(st + 2 * TILE_SB + so, Bh + go);
                cp16(st + 3 * TILE_SB + so, Bh + bps + go);
            }
        }
        cp_commit();
        cp_wait<STAGES - 1>();
        __syncthreads();

        const uint32_t st = sb + (i % STAGES) * STAGE_SB;
        const uint32_t aH = st + aoff;
        const uint32_t aL = aH + TILE_SB;
        const uint32_t bH = st + 2 * TILE_SB + boff;
        const uint32_t bL = bH + TILE_SB;

#pragma unroll
        for (int ks = 0; ks < 2; ks++) {
            uint32_t ah[4][4], al[4][4], bh[4][2], bl[4][2];
#pragma unroll
            for (int mt = 0; mt < 4; mt++) ldm_x4(ah[mt], aH + mt * (16 * PITCH) + ks * 32);
#pragma unroll
            for (int nt = 0; nt < 4; nt++) ldm_x2(bh[nt], bH + nt * (8 * PITCH) + ks * 32);
#pragma unroll
            for (int mt = 0; mt < 4; mt++)
#pragma unroll
                for (int nt = 0; nt < 4; nt++) mma_bf16(acc[mt][nt], ah[mt], bh[nt]);
#pragma unroll
            for (int nt = 0; nt < 4; nt++) ldm_x2(bl[nt], bL + nt * (8 * PITCH) + ks * 32);
#pragma unroll
            for (int mt = 0; mt < 4; mt++)
#pragma unroll
                for (int nt = 0; nt < 4; nt++) mma_bf16(acc[mt][nt], ah[mt], bl[nt]);
#pragma unroll
            for (int mt = 0; mt < 4; mt++) ldm_x4(al[mt], aL + mt * (16 * PITCH) + ks * 32);
#pragma unroll
            for (int mt = 0; mt < 4; mt++)
#pragma unroll
                for (int nt = 0; nt < 4; nt++) mma_bf16(acc[mt][nt], al[mt], bh[nt]);
        }
        __syncthreads();
    }

    // ---------------- epilogue: bias + act + dual-plane bf16 store ----------
    const int lr = lane >> 2;       // 0..7
    const int lc = (lane & 3) * 2;  // 0,2,4,6
#pragma unroll
    for (int mt = 0; mt < 4; mt++) {
#pragma unroll
        for (int nt = 0; nt < 4; nt++) {
            const size_t r0 = row0 + wm * 64 + mt * 16 + lr;
            const size_t cc = col0 + wn * 32 + nt * 8 + lc;
            const float bx = __ldg(bias + cc);
            const float by = __ldg(bias + cc + 1);
#pragma unroll
            for (int hh = 0; hh < 2; hh++) {
                const size_t r = r0 + hh * 8;
                const float v0 = apply_act<ACT>(acc[mt][nt][hh * 2 + 0] + bx);
                const float v1 = apply_act<ACT>(acc[mt][nt][hh * 2 + 1] + by);
                __nv_bfloat16 h0, l0, h1, l1;
                split_bf16(v0, h0, l0);
                split_bf16(v1, h1, l1);
                __nv_bfloat16 hp[2] = {h0, h1}, lp[2] = {l0, l1};
                const size_t o = r * N + cc;
                *(uint32_t*)(C + o)       = *(uint32_t*)hp;
                *(uint32_t*)(C + cps + o) = *(uint32_t*)lp;
            }
        }
    }
}

// ---------------------------------------------------------------------------
// launch
// ---------------------------------------------------------------------------
static inline dim3 gemm_grid(int M, int N) { return dim3(N / 128, M / 128); }

extern "C" void kernel_launch(void* const* d_in, const int* in_sizes, int n_in,
                              void* d_out, int out_size)
{
    const int*   leaf = (const int*)  d_in[0];
    const float* ent  = (const float*)d_in[1];
    const float* th   = (const float*)d_in[2];
    const float* w1   = (const float*)d_in[3];
    const float* b1   = (const float*)d_in[4];
    const float* w2   = (const float*)d_in[5];
    const float* b2   = (const float*)d_in[6];
    const float* o1   = (const float*)d_in[7];
    const float* ob1  = (const float*)d_in[8];
    const float* o2   = (const float*)d_in[9];
    const float* ob2  = (const float*)d_in[10];
    const float* h1   = (const float*)d_in[11];
    const float* hb1  = (const float*)d_in[12];
    const float* h2   = (const float*)d_in[13];
    const float* hb2  = (const float*)d_in[14];
    const float* h3   = (const float*)d_in[15];
    const float* hb3  = (const float*)d_in[16];
    const float* h4   = (const float*)d_in[17];
    const float* hb4  = (const float*)d_in[18];

    __nv_bfloat16 *bufA, *bufB, *H, *feat, *z1, *z2, *z3, *wT;
    cudaGetSymbolAddress((void**)&bufA, g_bufA);
    cudaGetSymbolAddress((void**)&bufB, g_bufB);
    cudaGetSymbolAddress((void**)&H,    g_bufH);
    cudaGetSymbolAddress((void**)&feat, g_feat);
    cudaGetSymbolAddress((void**)&z1,   g_z1);
    cudaGetSymbolAddress((void**)&z2,   g_z2);
    cudaGetSymbolAddress((void**)&z3,   g_z3);
    cudaGetSymbolAddress((void**)&wT,   g_wT);

    cudaFuncSetAttribute(gemm_mma<ACT_RELU>,
                         cudaFuncAttributeMaxDynamicSharedMemorySize, GSMEM);
    cudaFuncSetAttribute(gemm_mma<ACT_TANH>,
                         cudaFuncAttributeMaxDynamicSharedMemorySize, GSMEM);

    // 0) weight transposes + bf16 split (prep)
    transpose_kernel<<<dim3(4 * E_ / 32, 2 * E_ / 32), dim3(32, 8)>>>(w1, wT + W1T_OFF, 2 * E_, 4 * E_);
    transpose_kernel<<<dim3(E_ / 32, 4 * E_ / 32),     dim3(32, 8)>>>(w2, wT + W2T_OFF, 4 * E_, E_);
    transpose_kernel<<<dim3(4 * E_ / 32, E_ / 32),     dim3(32, 8)>>>(o1, wT + O1T_OFF, E_, 4 * E_);
    transpose_kernel<<<dim3(E_ / 32, 4 * E_ / 32),     dim3(32, 8)>>>(o2, wT + O2T_OFF, 4 * E_, E_);
    transpose_kernel<<<dim3(E_ / 32, (T_ + NT_ * E_) / 32), dim3(32, 8)>>>(h1, wT + H1T_OFF, T_ + NT_ * E_, E_);
    transpose_kernel<<<dim3((E_/2) / 32, E_ / 32),     dim3(32, 8)>>>(h2, wT + H2T_OFF, E_, E_ / 2);
    transpose_kernel<<<dim3((E_/4) / 32, (E_/2) / 32), dim3(32, 8)>>>(h3, wT + H3T_OFF, E_ / 2, E_ / 4);

    // 1) leaf gather -> bufA planes [B*NT*NL, E]
    gather_kernel<<<B_ * NT_ * NL_, E_ / 4>>>(leaf, ent, bufA);

    // 2) tree reduction (6 levels)
    __nv_bfloat16* in  = bufA;  size_t in_s  = SA_;
    __nv_bfloat16* out = bufB;  size_t out_s = SB_;
    int n = NL_;
    while (n > 1) {
        const int rows = B_ * NT_ * (n / 2);
        gemm_mma<ACT_RELU><<<gemm_grid(rows, 4 * E_), 256, GSMEM>>>(
            in, in_s, wT + W1T_OFF, WPS_, b1, H, SH_, rows, 4 * E_, 2 * E_);
        gemm_mma<ACT_RELU><<<gemm_grid(rows, E_), 256, GSMEM>>>(
            H, SH_, wT + W2T_OFF, WPS_, b2, out, out_s, rows, E_, 4 * E_);
        __nv_bfloat16* tp = in; in = out; out = tp;
        size_t ts = in_s; in_s = out_s; out_s = ts;
        n >>= 1;
    }
    // root in `in`: [1024, 512]

    // 3) one2one
    {
        const int rows = B_ * NT_;
        gemm_mma<ACT_RELU><<<gemm_grid(rows, 4 * E_), 256, GSMEM>>>(
            in, in_s, wT + O1T_OFF, WPS_, ob1, H, SH_, rows, 4 * E_, E_);
        gemm_mma<ACT_TANH><<<gemm_grid(rows, E_), 256, GSMEM>>>(
            H, SH_, wT + O2T_OFF, WPS_, ob2, out, out_s, rows, E_, 4 * E_);
    }
    // root2 in `out` (plane stride out_s): [B, NT*E]

    // 4) feat = [th | root2]
    // note: out_s must equal SB_ or SA_; feat_kernel uses SB_-style stride via arg
    // root2 buffer plane stride is out_s; handle both by passing pointer math:
    feat_kernel<<<B_, (T_ + NT_ * E_) / 4>>>(th, out, feat);
    // feat_kernel assumes root2 lo at +SB_; ensure `out` is bufB:
    // (6 levels => even number of swaps in the while-loop: after 6 levels in=bufA,
    //  then one2one writes `out`=bufB. SB_ stride is correct.)

    // 5) head
    gemm_mma<ACT_RELU><<<gemm_grid(B_, E_), 256, GSMEM>>>(
        feat, SF_, wT + H1T_OFF, WPS_, hb1, z1, SZ1_, B_, E_, T_ + NT_ * E_);
    gemm_mma<ACT_RELU><<<gemm_grid(B_, E_ / 2), 256, GSMEM>>>(
        z1, SZ1_, wT + H2T_OFF, WPS_, hb2, z2, SZ2_, B_, E_ / 2, E_);
    gemm_mma<ACT_RELU><<<gemm_grid(B_, E_ / 4), 256, GSMEM>>>(
        z2, SZ2_, wT + H3T_OFF, WPS_, hb3, z3, SZ3_, B_, E_ / 4, E_ / 2);

    // 6) final dot + sigmoid
    final_kernel<<<(B_ * 32 + 255) / 256, 256>>>(z3, h4, hb4, (float*)d_out);
}

// round 4
// speedup vs baseline: 5.4463x; 2.6207x over previous
#include <cuda_runtime.h>
#include <cuda_fp16.h>
#include <math.h>
#include <stdint.h>

// ===========================================================================
// LogicRecursiveNN on GB300 (plain sm_103 PTX target -> mma.sync path).
// Single-pass fp16 GEMMs, f32 accumulate: per-GEMM rel err ~4e-4,
// chain-attenuated final err ~4e-5 (anchored on R3 measurement).
// Mainloop: 4-stage cp.async -> ldmatrix -> mma.sync m16n8k16.
// ===========================================================================

#define B_    512
#define NT_   2
#define NL_   64
#define E_    512
#define T_    512

#define SA_   ((size_t)B_ * NT_ * NL_ * E_)        // 33,554,432
#define SB_   ((size_t)B_ * NT_ * NL_ * E_ / 2)
#define SH_   ((size_t)B_ * NT_ * (NL_/2) * 4 * E_)
#define SF_   ((size_t)B_ * (T_ + NT_ * E_))
#define SZ1_  ((size_t)B_ * E_)
#define SZ2_  ((size_t)B_ * (E_/2))
#define SZ3_  ((size_t)B_ * (E_/4))

// device scratch: single-plane fp16 buffers
__device__ __half g_bufA[SA_];
__device__ __half g_bufB[SB_];
__device__ __half g_bufH[SH_];
__device__ __half g_feat[SF_];
__device__ __half g_z1[SZ1_];
__device__ __half g_z2[SZ2_];
__device__ __half g_z3[SZ3_];
__device__ __half g_wT[6193152];

// weight offsets (elements)
#define W1T_OFF  0          // [2048,1024]
#define W2T_OFF  2097152    // [512,2048]
#define O1T_OFF  3145728    // [2048,512]
#define O2T_OFF  4194304    // [512,2048]
#define H1T_OFF  5242880    // [512,1536]
#define H2T_OFF  6029312    // [256,512]
#define H3T_OFF  6160384    // [128,256]

// ---------------------------------------------------------------------------
// helpers
// ---------------------------------------------------------------------------
__device__ __forceinline__ uint32_t smem_u32(const void* p) {
    uint32_t a;
    asm("{ .reg .u64 t; cvta.to.shared.u64 t, %1; cvt.u32.u64 %0, t; }"
        : "=r"(a) : "l"(p));
    return a;
}
__device__ __forceinline__ void cp16(uint32_t dst, const void* src) {
    asm volatile("cp.async.cg.shared.global [%0], [%1], 16;"
                 :: "r"(dst), "l"(src) : "memory");
}
__device__ __forceinline__ void cp_commit() {
    asm volatile("cp.async.commit_group;" ::: "memory");
}
template <int N>
__device__ __forceinline__ void cp_wait() {
    asm volatile("cp.async.wait_group %0;" :: "n"(N) : "memory");
}
__device__ __forceinline__ void ldm_x4(uint32_t* r, uint32_t addr) {
    asm volatile("ldmatrix.sync.aligned.m8n8.x4.shared.b16 {%0,%1,%2,%3}, [%4];"
                 : "=r"(r[0]), "=r"(r[1]), "=r"(r[2]), "=r"(r[3]) : "r"(addr));
}
__device__ __forceinline__ void ldm_x2(uint32_t* r, uint32_t addr) {
    asm volatile("ldmatrix.sync.aligned.m8n8.x2.shared.b16 {%0,%1}, [%2];"
                 : "=r"(r[0]), "=r"(r[1]) : "r"(addr));
}
__device__ __forceinline__ void mma_f16(float* c, const uint32_t* a, const uint32_t* b) {
    asm volatile(
        "mma.sync.aligned.m16n8k16.row.col.f32.f16.f16.f32 "
        "{%0,%1,%2,%3}, {%4,%5,%6,%7}, {%8,%9}, {%0,%1,%2,%3};"
        : "+f"(c[0]), "+f"(c[1]), "+f"(c[2]), "+f"(c[3])
        : "r"(a[0]), "r"(a[1]), "r"(a[2]), "r"(a[3]), "r"(b[0]), "r"(b[1]));
}

// ---------------------------------------------------------------------------
// small kernels
// ---------------------------------------------------------------------------
__global__ void gather_kernel(const int* __restrict__ idx,
                              const float* __restrict__ emb,
                              __half* __restrict__ out)
{
    const int row = blockIdx.x;
    const int e = idx[row];
    const float4 v = ((const float4*)(emb + (size_t)e * E_))[threadIdx.x];
    __half h[4];
    h[0] = __float2half_rn(v.x); h[1] = __float2half_rn(v.y);
    h[2] = __float2half_rn(v.z); h[3] = __float2half_rn(v.w);
    *(uint2*)(out + (size_t)row * E_ + threadIdx.x * 4) = *(uint2*)h;
}

// W[K,N] f32 -> Wt [N,K] fp16; grid(N/32, K/32), block(32,8)
__global__ void transpose_kernel(const float* __restrict__ W,
                                 __half* __restrict__ Wt,
                                 int K, int N)
{
    __shared__ float t[32][33];
    const int bx = blockIdx.x * 32;
    const int by = blockIdx.y * 32;
    for (int i = threadIdx.y; i < 32; i += 8)
        t[i][threadIdx.x] = W[(size_t)(by + i) * N + bx + threadIdx.x];
    __syncthreads();
    for (int i = threadIdx.y; i < 32; i += 8)
        Wt[(size_t)(bx + i) * K + by + threadIdx.x] = __float2half_rn(t[threadIdx.x][i]);
}

__global__ void feat_kernel(const float* __restrict__ th,
                            const __half* __restrict__ root2,
                            __half* __restrict__ feat)
{
    const int b = blockIdx.x;
    const int t = threadIdx.x;  // 0..383
    const size_t o = (size_t)b * (T_ + NT_ * E_) + t * 4;
    if (t < T_ / 4) {
        const float4 v = ((const float4*)th)[t];
        __half h[4];
        h[0] = __float2half_rn(v.x); h[1] = __float2half_rn(v.y);
        h[2] = __float2half_rn(v.z); h[3] = __float2half_rn(v.w);
        *(uint2*)(feat + o) = *(uint2*)h;
    } else {
        *(uint2*)(feat + o) =
            *(const uint2*)(root2 + (size_t)b * (NT_ * E_) + (t - T_ / 4) * 4);
    }
}

__global__ void final_kernel(const __half* __restrict__ z3,
                             const float* __restrict__ w,
                             const float* __restrict__ b0,
                             float* __restrict__ out)
{
    const int warp = (blockIdx.x * blockDim.x + threadIdx.x) >> 5;
    const int lane = threadIdx.x & 31;
    if (warp >= B_) return;
    const size_t base = (size_t)warp * 128;
    float s = 0.0f;
#pragma unroll
    for (int i = lane; i < 128; i += 32)
        s = fmaf(__half2float(z3[base + i]), w[i], s);
#pragma unroll
    for (int o = 16; o > 0; o >>= 1) s += __shfl_down_sync(0xFFFFFFFFu, s, o);
    if (lane == 0) {
        const float x = s + b0[0];
        out[warp] = 1.0f / (1.0f + expf(-x));
    }
}

// ---------------------------------------------------------------------------
// GEMM: C = act(A @ Bt^T + bias), fp16 operands, f32 accum.
// CTA 128x128, 8 warps (2x4), warp tile 64x32, KC=32, 4-stage cp.async.
// ---------------------------------------------------------------------------
#define KC       32
#define STAGES   4
#define PITCH    80                          // 32 fp16 (64B) + 16B pad
#define TILE_SB  (128 * PITCH)               // 10240 B
#define STAGE_SB (2 * TILE_SB)               // 20480 B (A, B)
#define GSMEM    (STAGES * STAGE_SB)         // 81920 B

#define ACT_RELU 0
#define ACT_TANH 1

template <int ACT>
__device__ __forceinline__ float apply_act(float x) {
    if (ACT == ACT_RELU) return fmaxf(x, 0.0f);
    return tanhf(x);
}

template <int ACT>
__global__ void __launch_bounds__(256, 1)
gemm_mma(const __half* __restrict__ A,
         const __half* __restrict__ Bt,
         const float* __restrict__ bias,
         __half* __restrict__ C,
         int M, int N, int K)
{
    extern __shared__ char smem[];
    const uint32_t sb = smem_u32(smem);
    const int tid = threadIdx.x;
    const int wid = tid >> 5;
    const int lane = tid & 31;
    const int wm = wid >> 2;        // 0..1
    const int wn = wid & 3;         // 0..3

    const size_t row0 = (size_t)blockIdx.y * 128;
    const size_t col0 = (size_t)blockIdx.x * 128;
    const __half* Ag = A + row0 * K;
    const __half* Bg = Bt + col0 * K;

    const int seg = tid & 3;        // 16B chunk within 64B row
    const int rowc = tid >> 2;      // 0..63

    const int nk = K / KC;

    // prologue: stages 0..STAGES-2
#pragma unroll
    for (int c = 0; c < STAGES - 1; c++) {
        if (c < nk) {
            const uint32_t st = sb + c * STAGE_SB;
            const int k0 = c * KC;
#pragma unroll
            for (int h = 0; h < 2; h++) {
                const int r = rowc + h * 64;
                const size_t go = (size_t)r * K + k0 + seg * 8;
                const uint32_t so = r * PITCH + seg * 16;
                cp16(st + so, Ag + go);
                cp16(st + TILE_SB + so, Bg + go);
            }
        }
        cp_commit();
    }

    float acc[4][4][4];
#pragma unroll
    for (int i = 0; i < 4; i++)
#pragma unroll
        for (int j = 0; j < 4; j++)
#pragma unroll
            for (int k = 0; k < 4; k++) acc[i][j][k] = 0.0f;

    const uint32_t aoff = (uint32_t)((wm * 64 + (lane & 15)) * PITCH + (lane >> 4) * 16);
    const uint32_t boff = (uint32_t)((wn * 32 + (lane & 7)) * PITCH + ((lane >> 3) & 1) * 16);

    for (int i = 0; i < nk; i++) {
        cp_wait<STAGES - 2>();
        __syncthreads();

        const uint32_t st = sb + (i % STAGES) * STAGE_SB;
        const uint32_t aB = st + aoff;
        const uint32_t bB = st + TILE_SB + boff;

#pragma unroll
        for (int ks = 0; ks < 2; ks++) {
            uint32_t af[4][4], bf[4][2];
#pragma unroll
            for (int mt = 0; mt < 4; mt++) ldm_x4(af[mt], aB + mt * (16 * PITCH) + ks * 32);
#pragma unroll
            for (int nt = 0; nt < 4; nt++) ldm_x2(bf[nt], bB + nt * (8 * PITCH) + ks * 32);
#pragma unroll
            for (int mt = 0; mt < 4; mt++)
#pragma unroll
                for (int nt = 0; nt < 4; nt++) mma_f16(acc[mt][nt], af[mt], bf[nt]);
        }

        // issue stage i+STAGES-1 (safe: all warps past sync, done reading it)
        const int c = i + STAGES - 1;
        if (c < nk) {
            const uint32_t stw = sb + (c % STAGES) * STAGE_SB;
            const int k0 = c * KC;
#pragma unroll
            for (int h = 0; h < 2; h++) {
                const int r = rowc + h * 64;
                const size_t go = (size_t)r * K + k0 + seg * 8;
                const uint32_t so = r * PITCH + seg * 16;
                cp16(stw + so, Ag + go);
                cp16(stw + TILE_SB + so, Bg + go);
            }
        }
        cp_commit();
    }

    // epilogue: bias + act + fp16 store
    const int lr = lane >> 2;
    const int lc = (lane & 3) * 2;
#pragma unroll
    for (int mt = 0; mt < 4; mt++) {
#pragma unroll
        for (int nt = 0; nt < 4; nt++) {
            const size_t r0 = row0 + wm * 64 + mt * 16 + lr;
            const size_t cc = col0 + wn * 32 + nt * 8 + lc;
            const float bx = __ldg(bias + cc);
            const float by = __ldg(bias + cc + 1);
#pragma unroll
            for (int hh = 0; hh < 2; hh++) {
                const size_t r = r0 + hh * 8;
                __half hp[2];
                hp[0] = __float2half_rn(apply_act<ACT>(acc[mt][nt][hh * 2 + 0] + bx));
                hp[1] = __float2half_rn(apply_act<ACT>(acc[mt][nt][hh * 2 + 1] + by));
                *(uint32_t*)(C + r * N + cc) = *(uint32_t*)hp;
            }
        }
    }
}

// ---------------------------------------------------------------------------
// launch
// ---------------------------------------------------------------------------
static inline dim3 gemm_grid(int M, int N) { return dim3(N / 128, M / 128); }

extern "C" void kernel_launch(void* const* d_in, const int* in_sizes, int n_in,
                              void* d_out, int out_size)
{
    const int*   leaf = (const int*)  d_in[0];
    const float* ent  = (const float*)d_in[1];
    const float* th   = (const float*)d_in[2];
    const float* w1   = (const float*)d_in[3];
    const float* b1   = (const float*)d_in[4];
    const float* w2   = (const float*)d_in[5];
    const float* b2   = (const float*)d_in[6];
    const float* o1   = (const float*)d_in[7];
    const float* ob1  = (const float*)d_in[8];
    const float* o2   = (const float*)d_in[9];
    const float* ob2  = (const float*)d_in[10];
    const float* h1   = (const float*)d_in[11];
    const float* hb1  = (const float*)d_in[12];
    const float* h2   = (const float*)d_in[13];
    const float* hb2  = (const float*)d_in[14];
    const float* h3   = (const float*)d_in[15];
    const float* hb3  = (const float*)d_in[16];
    const float* h4   = (const float*)d_in[17];
    const float* hb4  = (const float*)d_in[18];

    __half *bufA, *bufB, *H, *feat, *z1, *z2, *z3, *wT;
    cudaGetSymbolAddress((void**)&bufA, g_bufA);
    cudaGetSymbolAddress((void**)&bufB, g_bufB);
    cudaGetSymbolAddress((void**)&H,    g_bufH);
    cudaGetSymbolAddress((void**)&feat, g_feat);
    cudaGetSymbolAddress((void**)&z1,   g_z1);
    cudaGetSymbolAddress((void**)&z2,   g_z2);
    cudaGetSymbolAddress((void**)&z3,   g_z3);
    cudaGetSymbolAddress((void**)&wT,   g_wT);

    cudaFuncSetAttribute(gemm_mma<ACT_RELU>,
                         cudaFuncAttributeMaxDynamicSharedMemorySize, GSMEM);
    cudaFuncSetAttribute(gemm_mma<ACT_TANH>,
                         cudaFuncAttributeMaxDynamicSharedMemorySize, GSMEM);

    // 0) weight transposes -> fp16 [N,K]
    transpose_kernel<<<dim3(4 * E_ / 32, 2 * E_ / 32), dim3(32, 8)>>>(w1, wT + W1T_OFF, 2 * E_, 4 * E_);
    transpose_kernel<<<dim3(E_ / 32, 4 * E_ / 32),     dim3(32, 8)>>>(w2, wT + W2T_OFF, 4 * E_, E_);
    transpose_kernel<<<dim3(4 * E_ / 32, E_ / 32),     dim3(32, 8)>>>(o1, wT + O1T_OFF, E_, 4 * E_);
    transpose_kernel<<<dim3(E_ / 32, 4 * E_ / 32),     dim3(32, 8)>>>(o2, wT + O2T_OFF, 4 * E_, E_);
    transpose_kernel<<<dim3(E_ / 32, (T_ + NT_ * E_) / 32), dim3(32, 8)>>>(h1, wT + H1T_OFF, T_ + NT_ * E_, E_);
    transpose_kernel<<<dim3((E_/2) / 32, E_ / 32),     dim3(32, 8)>>>(h2, wT + H2T_OFF, E_, E_ / 2);
    transpose_kernel<<<dim3((E_/4) / 32, (E_/2) / 32), dim3(32, 8)>>>(h3, wT + H3T_OFF, E_ / 2, E_ / 4);

    // 1) leaf gather -> bufA [B*NT*NL, E]
    gather_kernel<<<B_ * NT_ * NL_, E_ / 4>>>(leaf, ent, bufA);

    // 2) tree reduction (6 levels)
    __half* in  = bufA;
    __half* out = bufB;
    int n = NL_;
    while (n > 1) {
        const int rows = B_ * NT_ * (n / 2);
        gemm_mma<ACT_RELU><<<gemm_grid(rows, 4 * E_), 256, GSMEM>>>(
            in, wT + W1T_OFF, b1, H, rows, 4 * E_, 2 * E_);
        gemm_mma<ACT_RELU><<<gemm_grid(rows, E_), 256, GSMEM>>>(
            H, wT + W2T_OFF, b2, out, rows, E_, 4 * E_);
        __half* tp = in; in = out; out = tp;
        n >>= 1;
    }
    // root in `in` (= bufA after 6 swaps): [1024, 512]

    // 3) one2one
    {
        const int rows = B_ * NT_;
        gemm_mma<ACT_RELU><<<gemm_grid(rows, 4 * E_), 256, GSMEM>>>(
            in, wT + O1T_OFF, ob1, H, rows, 4 * E_, E_);
        gemm_mma<ACT_TANH><<<gemm_grid(rows, E_), 256, GSMEM>>>(
            H, wT + O2T_OFF, ob2, out, rows, E_, 4 * E_);
    }
    // root2 in `out` = bufB : [B, NT*E]

    // 4) feat = [th | root2]
    feat_kernel<<<B_, (T_ + NT_ * E_) / 4>>>(th, out, feat);

    // 5) head
    gemm_mma<ACT_RELU><<<gemm_grid(B_, E_), 256, GSMEM>>>(
        feat, wT + H1T_OFF, hb1, z1, B_, E_, T_ + NT_ * E_);
    gemm_mma<ACT_RELU><<<gemm_grid(B_, E_ / 2), 256, GSMEM>>>(
        z1, wT + H2T_OFF, hb2, z2, B_, E_ / 2, E_);
    gemm_mma<ACT_RELU><<<gemm_grid(B_, E_ / 4), 256, GSMEM>>>(
        z2, wT + H3T_OFF, hb3, z3, B_, E_ / 4, E_ / 2);

    // 6) final dot + sigmoid
    final_kernel<<<(B_ * 32 + 255) / 256, 256>>>(z3, h4, hb4, (float*)d_out);
}